// round 1
// baseline (speedup 1.0000x reference)
#include <cuda_runtime.h>
#include <cstdint>

// Problem constants
#define B_    4
#define S_    2048
#define D_    1024
#define H_    16
#define DK_   64
#define DFF_  4096
#define M_    (B_*S_)   // 8192 rows

// ---------------------------------------------------------------------------
// Static device scratch (allocation-free rule)
// ---------------------------------------------------------------------------
__device__ float g_xn[M_*D_];               // LN1 output
__device__ float g_q [M_*D_];               // Q proj out [M,D] (head h at cols h*64..)
__device__ float g_k [M_*D_];
__device__ float g_v [M_*D_];
__device__ float g_vt[M_*D_];               // V transposed: [B,H,DK,S]
__device__ float g_ao[M_*D_];               // attention output [B,S,D]
__device__ float g_h [M_*D_];               // residual 1
__device__ float g_hn[M_*D_];               // LN2 output
__device__ float g_f1[M_*DFF_];             // FFN hidden
__device__ float g_scores[268435456];       // [B*H, S, S] scores / probs (1 GB)

// ---------------------------------------------------------------------------
// Helpers
// ---------------------------------------------------------------------------
__device__ __forceinline__ float warpRedSum(float v){
    #pragma unroll
    for (int o=16;o;o>>=1) v += __shfl_xor_sync(0xffffffffu, v, o);
    return v;
}
__device__ __forceinline__ float warpRedMax(float v){
    #pragma unroll
    for (int o=16;o;o>>=1) v = fmaxf(v, __shfl_xor_sync(0xffffffffu, v, o));
    return v;
}

__device__ __forceinline__ float to_tf32(float x){
    uint32_t u;
    asm("cvt.rna.tf32.f32 %0, %1;" : "=r"(u) : "f"(x));
    return __uint_as_float(u);
}

__device__ __forceinline__ void mma8(float c[4], const uint32_t a[4], const uint32_t b[2]){
    asm volatile(
        "mma.sync.aligned.m16n8k8.row.col.f32.tf32.tf32.f32 "
        "{%0,%1,%2,%3}, {%4,%5,%6,%7}, {%8,%9}, {%0,%1,%2,%3};\n"
        : "+f"(c[0]), "+f"(c[1]), "+f"(c[2]), "+f"(c[3])
        : "r"(a[0]), "r"(a[1]), "r"(a[2]), "r"(a[3]),
          "r"(b[0]), "r"(b[1]));
}

// ---------------------------------------------------------------------------
// LayerNorm: one block per row of D_=1024. torch-style: a*(x-mean)/(std+eps)+c,
// std unbiased (ddof=1), eps added to std (not var).
// ---------------------------------------------------------------------------
__global__ void ln_kernel(const float* __restrict__ x,
                          const float* __restrict__ alpha,
                          const float* __restrict__ beta,
                          float* __restrict__ y)
{
    __shared__ float s1[8], s2[8];
    long row = blockIdx.x;
    const float4* xr = (const float4*)(x + row*(long)D_);
    float4 v = xr[threadIdx.x];                       // 256 threads * 4 = 1024
    float sum = v.x+v.y+v.z+v.w;
    float sq  = v.x*v.x+v.y*v.y+v.z*v.z+v.w*v.w;
    int lane = threadIdx.x & 31, w = threadIdx.x >> 5;
    sum = warpRedSum(sum); sq = warpRedSum(sq);
    if (lane==0){ s1[w]=sum; s2[w]=sq; }
    __syncthreads();
    if (w==0){
        float a = (lane<8)? s1[lane] : 0.f;
        float b = (lane<8)? s2[lane] : 0.f;
        a = warpRedSum(a); b = warpRedSum(b);
        if (lane==0){ s1[0]=a; s2[0]=b; }
    }
    __syncthreads();
    float mean = s1[0] * (1.f/D_);
    float var  = (s2[0] - (float)D_*mean*mean) * (1.f/(D_-1));
    var = fmaxf(var, 0.f);
    float inv = alpha[0] / (sqrtf(var) + 1e-6f);
    float c   = beta[0];
    float4 o;
    o.x=(v.x-mean)*inv+c; o.y=(v.y-mean)*inv+c;
    o.z=(v.z-mean)*inv+c; o.w=(v.w-mean)*inv+c;
    ((float4*)(y + row*(long)D_))[threadIdx.x] = o;
}

// ---------------------------------------------------------------------------
// Masked softmax, in-place over g_scores rows of length S_=2048.
// grid: (S_, B_*H_), block 256. mask[b, k] == 0 -> score := -1e9 (matches ref).
// ---------------------------------------------------------------------------
__global__ void softmax_kernel(float* __restrict__ sc, const int* __restrict__ mask)
{
    __shared__ float sh[8];
    int t = threadIdx.x, lane = t & 31, w = t >> 5;
    int q = blockIdx.x, bh = blockIdx.y, b = bh >> 4;      // H_=16
    float4* row = (float4*)(sc + ((long)bh*S_ + q)*(long)S_);
    const int4* mr = (const int4*)(mask + (long)b*S_);
    float4 v0 = row[t], v1 = row[t+256];
    int4 m0 = mr[t], m1 = mr[t+256];
    float vv[8];
    vv[0]=m0.x?v0.x:-1e9f; vv[1]=m0.y?v0.y:-1e9f; vv[2]=m0.z?v0.z:-1e9f; vv[3]=m0.w?v0.w:-1e9f;
    vv[4]=m1.x?v1.x:-1e9f; vv[5]=m1.y?v1.y:-1e9f; vv[6]=m1.z?v1.z:-1e9f; vv[7]=m1.w?v1.w:-1e9f;
    float mx = vv[0];
    #pragma unroll
    for (int i=1;i<8;i++) mx = fmaxf(mx, vv[i]);
    mx = warpRedMax(mx);
    if (lane==0) sh[w] = mx;
    __syncthreads();
    if (w==0){
        float a = (lane<8)? sh[lane] : -3.4e38f;
        a = warpRedMax(a);
        if (lane==0) sh[0] = a;
    }
    __syncthreads();
    float Mx = sh[0];
    __syncthreads();
    float e[8], sum = 0.f;
    #pragma unroll
    for (int i=0;i<8;i++){ e[i] = __expf(vv[i]-Mx); sum += e[i]; }
    sum = warpRedSum(sum);
    if (lane==0) sh[w] = sum;
    __syncthreads();
    if (w==0){
        float a = (lane<8)? sh[lane] : 0.f;
        a = warpRedSum(a);
        if (lane==0) sh[0] = a;
    }
    __syncthreads();
    float inv = 1.f / sh[0];
    v0 = make_float4(e[0]*inv, e[1]*inv, e[2]*inv, e[3]*inv);
    v1 = make_float4(e[4]*inv, e[5]*inv, e[6]*inv, e[7]*inv);
    row[t] = v0; row[t+256] = v1;
}

// ---------------------------------------------------------------------------
// V transpose: g_v [b*S+s][h*DK+dk]  ->  g_vt [(b*H+h)*DK+dk][s]
// grid (S_/32, DK_/32, B_*H_), block (32,8)
// ---------------------------------------------------------------------------
__global__ void vtrans_kernel()
{
    __shared__ float tile[32][33];
    int bh = blockIdx.z, b = bh >> 4, h = bh & 15;
    const float* In = g_v + (long)b*S_*D_ + h*DK_;     // [s][dk], stride D_
    float* Out = g_vt + (long)bh*DK_*S_;               // [dk][s], stride S_
    int s0 = blockIdx.x*32, d0 = blockIdx.y*32;
    int tx = threadIdx.x, ty = threadIdx.y;
    #pragma unroll
    for (int j=0;j<32;j+=8)
        tile[ty+j][tx] = In[(long)(s0+ty+j)*D_ + d0+tx];
    __syncthreads();
    #pragma unroll
    for (int j=0;j<32;j+=8)
        Out[(long)(d0+ty+j)*S_ + s0+tx] = tile[tx][ty+j];
}

// ---------------------------------------------------------------------------
// Generic NT GEMM with tf32 tensor cores:
//   C[m,n] = scale * sum_k A[m,k]*B[n,k]  (+bias[n]) (+relu) (+resid[m,n])
// Batched over blockIdx.z decomposed as (zb = z/16, zh = z%16) with per-operand
// strides. BM x BN x 32 CTA tile, 8 warps (2 M x 4 N), each warp WMxWN.
// Requires: M % BM == 0, N % BN == 0, K % 32 == 0 (all call sites satisfy).
// ---------------------------------------------------------------------------
template<int BM, int BN, bool HAS_BIAS, bool RELU, bool HAS_RESID>
__global__ __launch_bounds__(256) void gemm_tf32(
    const float* __restrict__ A, int lda, long aSb, long aSh,
    const float* __restrict__ Bm, int ldb, long bSb, long bSh,
    float* __restrict__ C, int ldc, long cSb, long cSh,
    const float* __restrict__ bias, const float* __restrict__ resid,
    int K, float scale)
{
    constexpr int BK = 32;
    constexpr int WM = BM/2, WN = BN/4;
    constexpr int MF = WM/16, NF = WN/8;

    int z = blockIdx.z, zb = z >> 4, zh = z & 15;
    const float* Ab = A  + (long)zb*aSb + (long)zh*aSh;
    const float* Bb = Bm + (long)zb*bSb + (long)zh*bSh;
    long co = (long)zb*cSb + (long)zh*cSh;
    float* Cb = C + co;

    __shared__ __align__(16) float As[BM][36];
    __shared__ __align__(16) float Bs[BN][36];

    int tid = threadIdx.x, lane = tid & 31, warp = tid >> 5;
    int g = lane >> 2, tg = lane & 3;
    int wm = warp >> 2, wn = warp & 3;
    int m0 = blockIdx.y * BM, n0 = blockIdx.x * BN;

    float acc[MF][NF][4];
    #pragma unroll
    for (int i=0;i<MF;i++)
        #pragma unroll
        for (int j=0;j<NF;j++)
            #pragma unroll
            for (int r=0;r<4;r++) acc[i][j][r] = 0.f;

    for (int k0 = 0; k0 < K; k0 += BK){
        // load A tile (BM x 32 floats, float4 vectorized, tf32-rounded)
        #pragma unroll
        for (int i = 0; i < BM*BK/4; i += 256){
            int idx = i + tid;
            int r = idx >> 3, c = idx & 7;
            float4 v = *(const float4*)(Ab + (long)(m0+r)*lda + k0 + c*4);
            float4 t4;
            t4.x = to_tf32(v.x); t4.y = to_tf32(v.y);
            t4.z = to_tf32(v.z); t4.w = to_tf32(v.w);
            *(float4*)&As[r][c*4] = t4;
        }
        // load B tile (BN x 32)
        #pragma unroll
        for (int i = 0; i < BN*BK/4; i += 256){
            int idx = i + tid;
            int r = idx >> 3, c = idx & 7;
            float4 v = *(const float4*)(Bb + (long)(n0+r)*ldb + k0 + c*4);
            float4 t4;
            t4.x = to_tf32(v.x); t4.y = to_tf32(v.y);
            t4.z = to_tf32(v.z); t4.w = to_tf32(v.w);
            *(float4*)&Bs[r][c*4] = t4;
        }
        __syncthreads();

        #pragma unroll
        for (int ks = 0; ks < BK; ks += 8){
            uint32_t af[MF][4], bf[NF][2];
            #pragma unroll
            for (int im=0; im<MF; im++){
                int r = wm*WM + im*16 + g;
                af[im][0] = __float_as_uint(As[r  ][ks+tg  ]);
                af[im][1] = __float_as_uint(As[r+8][ks+tg  ]);
                af[im][2] = __float_as_uint(As[r  ][ks+tg+4]);
                af[im][3] = __float_as_uint(As[r+8][ks+tg+4]);
            }
            #pragma unroll
            for (int jn=0; jn<NF; jn++){
                int r = wn*WN + jn*8 + g;
                bf[jn][0] = __float_as_uint(Bs[r][ks+tg  ]);
                bf[jn][1] = __float_as_uint(Bs[r][ks+tg+4]);
            }
            #pragma unroll
            for (int im=0; im<MF; im++)
                #pragma unroll
                for (int jn=0; jn<NF; jn++)
                    mma8(acc[im][jn], af[im], bf[jn]);
        }
        __syncthreads();
    }

    // epilogue
    #pragma unroll
    for (int im=0; im<MF; im++){
        int rbase = m0 + wm*WM + im*16 + g;
        #pragma unroll
        for (int jn=0; jn<NF; jn++){
            int cbase = n0 + wn*WN + jn*8 + tg*2;
            #pragma unroll
            for (int p=0; p<2; p++){
                int col = cbase + p;
                float bv = HAS_BIAS ? bias[col] : 0.f;
                float v0 = acc[im][jn][p]   * scale + bv;
                float v1 = acc[im][jn][p+2] * scale + bv;
                if (RELU){ v0 = fmaxf(v0, 0.f); v1 = fmaxf(v1, 0.f); }
                if (HAS_RESID){
                    const float* Rb = resid + co;
                    v0 += Rb[(long)rbase*ldc + col];
                    v1 += Rb[(long)(rbase+8)*ldc + col];
                }
                Cb[(long)rbase*ldc + col]     = v0;
                Cb[(long)(rbase+8)*ldc + col] = v1;
            }
        }
    }
}

// ---------------------------------------------------------------------------
// Launch
// ---------------------------------------------------------------------------
extern "C" void kernel_launch(void* const* d_in, const int* in_sizes, int n_in,
                              void* d_out, int out_size)
{
    const float* x    = (const float*)d_in[0];
    const int*   mask = (const int*)  d_in[1];
    const float* wq = (const float*)d_in[2];  const float* bq = (const float*)d_in[3];
    const float* wk = (const float*)d_in[4];  const float* bk = (const float*)d_in[5];
    const float* wv = (const float*)d_in[6];  const float* bv = (const float*)d_in[7];
    const float* wo = (const float*)d_in[8];  const float* bo = (const float*)d_in[9];
    const float* w1 = (const float*)d_in[10]; const float* b1 = (const float*)d_in[11];
    const float* w2 = (const float*)d_in[12]; const float* b2 = (const float*)d_in[13];
    const float* a1 = (const float*)d_in[14]; const float* c1 = (const float*)d_in[15];
    const float* a2 = (const float*)d_in[16]; const float* c2 = (const float*)d_in[17];
    float* out = (float*)d_out;

    void* p;
    float *xn,*q,*k,*v,*vt,*ao,*h,*hn,*f1,*sc;
    cudaGetSymbolAddress(&p, g_xn); xn = (float*)p;
    cudaGetSymbolAddress(&p, g_q ); q  = (float*)p;
    cudaGetSymbolAddress(&p, g_k ); k  = (float*)p;
    cudaGetSymbolAddress(&p, g_v ); v  = (float*)p;
    cudaGetSymbolAddress(&p, g_vt); vt = (float*)p;
    cudaGetSymbolAddress(&p, g_ao); ao = (float*)p;
    cudaGetSymbolAddress(&p, g_h ); h  = (float*)p;
    cudaGetSymbolAddress(&p, g_hn); hn = (float*)p;
    cudaGetSymbolAddress(&p, g_f1); f1 = (float*)p;
    cudaGetSymbolAddress(&p, g_scores); sc = (float*)p;

    // 1) LN1
    ln_kernel<<<M_, 256>>>(x, a1, c1, xn);

    // 2) Q, K, V projections: [8192,1024] @ [1024,1024]^T
    dim3 gp(D_/128, M_/128, 1);
    gemm_tf32<128,128,true,false,false><<<gp,256>>>(
        xn, D_, 0,0,  wq, D_, 0,0,  q, D_, 0,0,  bq, nullptr, D_, 1.f);
    gemm_tf32<128,128,true,false,false><<<gp,256>>>(
        xn, D_, 0,0,  wk, D_, 0,0,  k, D_, 0,0,  bk, nullptr, D_, 1.f);
    gemm_tf32<128,128,true,false,false><<<gp,256>>>(
        xn, D_, 0,0,  wv, D_, 0,0,  v, D_, 0,0,  bv, nullptr, D_, 1.f);

    // 3) transpose V -> [B,H,DK,S]
    vtrans_kernel<<<dim3(S_/32, DK_/32, B_*H_), dim3(32,8)>>>();

    // 4) scores = Q K^T / sqrt(64), per (b,h)
    dim3 gs(S_/128, S_/128, B_*H_);
    gemm_tf32<128,128,false,false,false><<<gs,256>>>(
        q,  D_, (long)S_*D_, DK_,
        k,  D_, (long)S_*D_, DK_,
        sc, S_, (long)H_*S_*S_, (long)S_*S_,
        nullptr, nullptr, DK_, 0.125f);

    // 5) masked softmax (in place)
    softmax_kernel<<<dim3(S_, B_*H_), 256>>>(sc, mask);

    // 6) attention out = P @ V, per (b,h):  [2048,2048] @ [2048,64]
    dim3 gpv(1, S_/128, B_*H_);
    gemm_tf32<128,64,false,false,false><<<gpv,256>>>(
        sc, S_, (long)H_*S_*S_, (long)S_*S_,
        vt, S_, (long)H_*DK_*S_, (long)DK_*S_,
        ao, D_, (long)S_*D_, DK_,
        nullptr, nullptr, S_, 1.f);

    // 7) O projection + residual x
    gemm_tf32<128,128,true,false,true><<<gp,256>>>(
        ao, D_, 0,0,  wo, D_, 0,0,  h, D_, 0,0,  bo, x, D_, 1.f);

    // 8) LN2
    ln_kernel<<<M_, 256>>>(h, a2, c2, hn);

    // 9) FFN1 + ReLU: [8192,1024] @ [4096,1024]^T
    dim3 gf1(DFF_/128, M_/128, 1);
    gemm_tf32<128,128,true,true,false><<<gf1,256>>>(
        hn, D_, 0,0,  w1, D_, 0,0,  f1, DFF_, 0,0,  b1, nullptr, D_, 1.f);

    // 10) FFN2 + residual h -> out
    gemm_tf32<128,128,true,false,true><<<gp,256>>>(
        f1, DFF_, 0,0,  w2, DFF_, 0,0,  out, D_, 0,0,  b2, h, DFF_, 1.f);
}

// round 2
// speedup vs baseline: 1.2477x; 1.2477x over previous
#include <cuda_runtime.h>
#include <cstdint>

// Problem constants
#define B_    4
#define S_    2048
#define D_    1024
#define H_    16
#define DK_   64
#define DFF_  4096
#define M_    (B_*S_)   // 8192 rows

// ---------------------------------------------------------------------------
// Static device scratch (allocation-free rule)
// ---------------------------------------------------------------------------
__device__ float g_xn[M_*D_];               // LN1 output
__device__ float g_q [M_*D_];               // Q proj out
__device__ float g_k [M_*D_];
__device__ float g_v [M_*D_];
__device__ float g_vt[M_*D_];               // V transposed: [B,H,DK,S]
__device__ float g_ao[M_*D_];               // attention output [B,S,D]
__device__ float g_h [M_*D_];               // residual 1
__device__ float g_hn[M_*D_];               // LN2 output
__device__ float g_f1[M_*DFF_];             // FFN hidden
__device__ float g_scores[268435456];       // [B*H, S, S] scores / probs (1 GB)

// ---------------------------------------------------------------------------
// Helpers
// ---------------------------------------------------------------------------
__device__ __forceinline__ float warpRedSum(float v){
    #pragma unroll
    for (int o=16;o;o>>=1) v += __shfl_xor_sync(0xffffffffu, v, o);
    return v;
}
__device__ __forceinline__ float warpRedMax(float v){
    #pragma unroll
    for (int o=16;o;o>>=1) v = fmaxf(v, __shfl_xor_sync(0xffffffffu, v, o));
    return v;
}

__device__ __forceinline__ void mma8(float c[4], const uint32_t a[4], const uint32_t b[2]){
    asm volatile(
        "mma.sync.aligned.m16n8k8.row.col.f32.tf32.tf32.f32 "
        "{%0,%1,%2,%3}, {%4,%5,%6,%7}, {%8,%9}, {%0,%1,%2,%3};\n"
        : "+f"(c[0]), "+f"(c[1]), "+f"(c[2]), "+f"(c[3])
        : "r"(a[0]), "r"(a[1]), "r"(a[2]), "r"(a[3]),
          "r"(b[0]), "r"(b[1]));
}

__device__ __forceinline__ void cpa16(uint32_t dst, const void* src){
    asm volatile("cp.async.cg.shared.global [%0], [%1], 16;\n" :: "r"(dst), "l"(src));
}

// ---------------------------------------------------------------------------
// LayerNorm (torch-style: a*(x-mean)/(std+eps)+c, std unbiased, eps on std)
// ---------------------------------------------------------------------------
__global__ void ln_kernel(const float* __restrict__ x,
                          const float* __restrict__ alpha,
                          const float* __restrict__ beta,
                          float* __restrict__ y)
{
    __shared__ float s1[8], s2[8];
    long row = blockIdx.x;
    const float4* xr = (const float4*)(x + row*(long)D_);
    float4 v = xr[threadIdx.x];
    float sum = v.x+v.y+v.z+v.w;
    float sq  = v.x*v.x+v.y*v.y+v.z*v.z+v.w*v.w;
    int lane = threadIdx.x & 31, w = threadIdx.x >> 5;
    sum = warpRedSum(sum); sq = warpRedSum(sq);
    if (lane==0){ s1[w]=sum; s2[w]=sq; }
    __syncthreads();
    if (w==0){
        float a = (lane<8)? s1[lane] : 0.f;
        float b = (lane<8)? s2[lane] : 0.f;
        a = warpRedSum(a); b = warpRedSum(b);
        if (lane==0){ s1[0]=a; s2[0]=b; }
    }
    __syncthreads();
    float mean = s1[0] * (1.f/D_);
    float var  = (s2[0] - (float)D_*mean*mean) * (1.f/(D_-1));
    var = fmaxf(var, 0.f);
    float inv = alpha[0] / (sqrtf(var) + 1e-6f);
    float c   = beta[0];
    float4 o;
    o.x=(v.x-mean)*inv+c; o.y=(v.y-mean)*inv+c;
    o.z=(v.z-mean)*inv+c; o.w=(v.w-mean)*inv+c;
    ((float4*)(y + row*(long)D_))[threadIdx.x] = o;
}

// ---------------------------------------------------------------------------
// Masked softmax, in-place over rows of length S_
// ---------------------------------------------------------------------------
__global__ void softmax_kernel(float* __restrict__ sc, const int* __restrict__ mask)
{
    __shared__ float sh[8];
    int t = threadIdx.x, lane = t & 31, w = t >> 5;
    int q = blockIdx.x, bh = blockIdx.y, b = bh >> 4;
    float4* row = (float4*)(sc + ((long)bh*S_ + q)*(long)S_);
    const int4* mr = (const int4*)(mask + (long)b*S_);
    float4 v0 = row[t], v1 = row[t+256];
    int4 m0 = mr[t], m1 = mr[t+256];
    float vv[8];
    vv[0]=m0.x?v0.x:-1e9f; vv[1]=m0.y?v0.y:-1e9f; vv[2]=m0.z?v0.z:-1e9f; vv[3]=m0.w?v0.w:-1e9f;
    vv[4]=m1.x?v1.x:-1e9f; vv[5]=m1.y?v1.y:-1e9f; vv[6]=m1.z?v1.z:-1e9f; vv[7]=m1.w?v1.w:-1e9f;
    float mx = vv[0];
    #pragma unroll
    for (int i=1;i<8;i++) mx = fmaxf(mx, vv[i]);
    mx = warpRedMax(mx);
    if (lane==0) sh[w] = mx;
    __syncthreads();
    if (w==0){
        float a = (lane<8)? sh[lane] : -3.4e38f;
        a = warpRedMax(a);
        if (lane==0) sh[0] = a;
    }
    __syncthreads();
    float Mx = sh[0];
    __syncthreads();
    float e[8], sum = 0.f;
    #pragma unroll
    for (int i=0;i<8;i++){ e[i] = __expf(vv[i]-Mx); sum += e[i]; }
    sum = warpRedSum(sum);
    if (lane==0) sh[w] = sum;
    __syncthreads();
    if (w==0){
        float a = (lane<8)? sh[lane] : 0.f;
        a = warpRedSum(a);
        if (lane==0) sh[0] = a;
    }
    __syncthreads();
    float inv = 1.f / sh[0];
    v0 = make_float4(e[0]*inv, e[1]*inv, e[2]*inv, e[3]*inv);
    v1 = make_float4(e[4]*inv, e[5]*inv, e[6]*inv, e[7]*inv);
    row[t] = v0; row[t+256] = v1;
}

// ---------------------------------------------------------------------------
// V transpose: g_v [b*S+s][h*DK+dk]  ->  g_vt [(b*H+h)*DK+dk][s]
// ---------------------------------------------------------------------------
__global__ void vtrans_kernel()
{
    __shared__ float tile[32][33];
    int bh = blockIdx.z, b = bh >> 4, h = bh & 15;
    const float* In = g_v + (long)b*S_*D_ + h*DK_;
    float* Out = g_vt + (long)bh*DK_*S_;
    int s0 = blockIdx.x*32, d0 = blockIdx.y*32;
    int tx = threadIdx.x, ty = threadIdx.y;
    #pragma unroll
    for (int j=0;j<32;j+=8)
        tile[ty+j][tx] = In[(long)(s0+ty+j)*D_ + d0+tx];
    __syncthreads();
    #pragma unroll
    for (int j=0;j<32;j+=8)
        Out[(long)(d0+ty+j)*S_ + s0+tx] = tile[tx][ty+j];
}

// ---------------------------------------------------------------------------
// NT GEMM, tf32 tensor cores, cp.async double-buffered:
//   C[m,n] = scale * sum_k A[m,k]*B[n,k]  (+bias[n]) (+relu) (+resid[m,n])
// Batched over blockIdx.z as (zb = z/16, zh = z%16).
// BM x BN x 32 tile, WR x WC warps, warp tile (BM/WR) x (BN/WC).
// Raw fp32 bits fed to mma.tf32 (HW truncates mantissa).
// ---------------------------------------------------------------------------
template<int BM,int BN,int WR,int WC,bool HAS_BIAS,bool RELU,bool HAS_RESID>
__global__ __launch_bounds__(WR*WC*32, 1) void gemm2(
    const float* __restrict__ A, int lda, long aSb, long aSh,
    const float* __restrict__ Bm, int ldb, long bSb, long bSh,
    float* __restrict__ C, int ldc, long cSb, long cSh,
    const float* __restrict__ bias, const float* __restrict__ resid,
    int K, float scale)
{
    constexpr int BK = 32, LDSW = 36;
    constexpr int NT = WR*WC*32;
    constexpr int WM = BM/WR, WN = BN/WC;
    constexpr int MF = WM/16, NF = WN/8;
    constexpr int ASZ = BM*LDSW, BSZ = BN*LDSW;

    extern __shared__ float smemf[];
    float* As = smemf;              // 2 buffers of ASZ
    float* Bs = smemf + 2*ASZ;      // 2 buffers of BSZ

    int z = blockIdx.z, zb = z >> 4, zh = z & 15;
    const float* Ab = A  + (long)zb*aSb + (long)zh*aSh;
    const float* Bb = Bm + (long)zb*bSb + (long)zh*bSh;
    long co = (long)zb*cSb + (long)zh*cSh;

    int tid = threadIdx.x, lane = tid & 31, warp = tid >> 5;
    int g = lane >> 2, tg = lane & 3;
    int wm = warp / WC, wn = warp % WC;
    int m0 = blockIdx.y * BM, n0 = blockIdx.x * BN;

    uint32_t sbase = (uint32_t)__cvta_generic_to_shared(smemf);

    float acc[MF][NF][4];
    #pragma unroll
    for (int i=0;i<MF;i++)
        #pragma unroll
        for (int j=0;j<NF;j++)
            #pragma unroll
            for (int r=0;r<4;r++) acc[i][j][r] = 0.f;

    auto loadt = [&](int k0, int buf){
        #pragma unroll
        for (int i = 0; i < BM*8; i += NT){
            int idx = i + tid; int r = idx >> 3, c = idx & 7;
            cpa16(sbase + (uint32_t)((buf*ASZ + r*LDSW + c*4)*4),
                  Ab + (long)(m0+r)*lda + k0 + c*4);
        }
        #pragma unroll
        for (int i = 0; i < BN*8; i += NT){
            int idx = i + tid; int r = idx >> 3, c = idx & 7;
            cpa16(sbase + (uint32_t)((2*ASZ + buf*BSZ + r*LDSW + c*4)*4),
                  Bb + (long)(n0+r)*ldb + k0 + c*4);
        }
        asm volatile("cp.async.commit_group;\n");
    };

    int nt = K / BK;
    loadt(0, 0);

    for (int k0 = 0; k0 < nt; k0++){
        int cur = k0 & 1;
        if (k0+1 < nt){
            loadt((k0+1)*BK, cur^1);
            asm volatile("cp.async.wait_group 1;\n");
        } else {
            asm volatile("cp.async.wait_group 0;\n");
        }
        __syncthreads();

        const float* Asb = As + cur*ASZ;
        const float* Bsb = Bs + cur*BSZ;

        #pragma unroll
        for (int ks = 0; ks < BK; ks += 8){
            uint32_t af[MF][4], bf[NF][2];
            #pragma unroll
            for (int im=0; im<MF; im++){
                int r = wm*WM + im*16 + g;
                af[im][0] = __float_as_uint(Asb[r*LDSW + ks+tg  ]);
                af[im][1] = __float_as_uint(Asb[(r+8)*LDSW + ks+tg  ]);
                af[im][2] = __float_as_uint(Asb[r*LDSW + ks+tg+4]);
                af[im][3] = __float_as_uint(Asb[(r+8)*LDSW + ks+tg+4]);
            }
            #pragma unroll
            for (int jn=0; jn<NF; jn++){
                int r = wn*WN + jn*8 + g;
                bf[jn][0] = __float_as_uint(Bsb[r*LDSW + ks+tg  ]);
                bf[jn][1] = __float_as_uint(Bsb[r*LDSW + ks+tg+4]);
            }
            #pragma unroll
            for (int im=0; im<MF; im++)
                #pragma unroll
                for (int jn=0; jn<NF; jn++)
                    mma8(acc[im][jn], af[im], bf[jn]);
        }
        __syncthreads();
    }

    // epilogue (float2 stores)
    #pragma unroll
    for (int im=0; im<MF; im++){
        int r0 = m0 + wm*WM + im*16 + g;
        #pragma unroll
        for (int jn=0; jn<NF; jn++){
            int c0 = n0 + wn*WN + jn*8 + tg*2;
            float2 bv = HAS_BIAS ? *(const float2*)(bias + c0) : make_float2(0.f,0.f);
            float2 v0, v1;
            v0.x = acc[im][jn][0]*scale + bv.x;
            v0.y = acc[im][jn][1]*scale + bv.y;
            v1.x = acc[im][jn][2]*scale + bv.x;
            v1.y = acc[im][jn][3]*scale + bv.y;
            if (RELU){
                v0.x = fmaxf(v0.x,0.f); v0.y = fmaxf(v0.y,0.f);
                v1.x = fmaxf(v1.x,0.f); v1.y = fmaxf(v1.y,0.f);
            }
            if (HAS_RESID){
                const float* Rb = resid + co;
                float2 ra = *(const float2*)(Rb + (long)r0*ldc + c0);
                float2 rb = *(const float2*)(Rb + (long)(r0+8)*ldc + c0);
                v0.x += ra.x; v0.y += ra.y; v1.x += rb.x; v1.y += rb.y;
            }
            *(float2*)(C + co + (long)r0*ldc + c0)     = v0;
            *(float2*)(C + co + (long)(r0+8)*ldc + c0) = v1;
        }
    }
}

// ---------------------------------------------------------------------------
// Launch
// ---------------------------------------------------------------------------
extern "C" void kernel_launch(void* const* d_in, const int* in_sizes, int n_in,
                              void* d_out, int out_size)
{
    const float* x    = (const float*)d_in[0];
    const int*   mask = (const int*)  d_in[1];
    const float* wq = (const float*)d_in[2];  const float* bq = (const float*)d_in[3];
    const float* wk = (const float*)d_in[4];  const float* bk = (const float*)d_in[5];
    const float* wv = (const float*)d_in[6];  const float* bv = (const float*)d_in[7];
    const float* wo = (const float*)d_in[8];  const float* bo = (const float*)d_in[9];
    const float* w1 = (const float*)d_in[10]; const float* b1 = (const float*)d_in[11];
    const float* w2 = (const float*)d_in[12]; const float* b2 = (const float*)d_in[13];
    const float* a1 = (const float*)d_in[14]; const float* c1 = (const float*)d_in[15];
    const float* a2 = (const float*)d_in[16]; const float* c2 = (const float*)d_in[17];
    float* out = (float*)d_out;

    void* p;
    float *xn,*q,*k,*v,*vt,*ao,*h,*hn,*f1,*sc;
    cudaGetSymbolAddress(&p, g_xn); xn = (float*)p;
    cudaGetSymbolAddress(&p, g_q ); q  = (float*)p;
    cudaGetSymbolAddress(&p, g_k ); k  = (float*)p;
    cudaGetSymbolAddress(&p, g_v ); v  = (float*)p;
    cudaGetSymbolAddress(&p, g_vt); vt = (float*)p;
    cudaGetSymbolAddress(&p, g_ao); ao = (float*)p;
    cudaGetSymbolAddress(&p, g_h ); h  = (float*)p;
    cudaGetSymbolAddress(&p, g_hn); hn = (float*)p;
    cudaGetSymbolAddress(&p, g_f1); f1 = (float*)p;
    cudaGetSymbolAddress(&p, g_scores); sc = (float*)p;

    constexpr int SMEM_BIG = (2*128 + 2*256)*36*4;   // 110592 B
    constexpr int SMEM_PV  = (2*128 + 2*64 )*36*4;   // 55296 B

    cudaFuncSetAttribute((const void*)gemm2<128,256,2,4,true ,false,false>,
                         cudaFuncAttributeMaxDynamicSharedMemorySize, SMEM_BIG);
    cudaFuncSetAttribute((const void*)gemm2<128,256,2,4,false,false,false>,
                         cudaFuncAttributeMaxDynamicSharedMemorySize, SMEM_BIG);
    cudaFuncSetAttribute((const void*)gemm2<128,256,2,4,true ,false,true >,
                         cudaFuncAttributeMaxDynamicSharedMemorySize, SMEM_BIG);
    cudaFuncSetAttribute((const void*)gemm2<128,256,2,4,true ,true ,false>,
                         cudaFuncAttributeMaxDynamicSharedMemorySize, SMEM_BIG);
    cudaFuncSetAttribute((const void*)gemm2<128,64 ,2,4,false,false,false>,
                         cudaFuncAttributeMaxDynamicSharedMemorySize, SMEM_PV);

    // 1) LN1
    ln_kernel<<<M_, 256>>>(x, a1, c1, xn);

    // 2) Q, K, V projections: [8192,1024] @ [1024,1024]^T
    dim3 gp(D_/256, M_/128, 1);
    gemm2<128,256,2,4,true,false,false><<<gp,256,SMEM_BIG>>>(
        xn, D_, 0,0,  wq, D_, 0,0,  q, D_, 0,0,  bq, nullptr, D_, 1.f);
    gemm2<128,256,2,4,true,false,false><<<gp,256,SMEM_BIG>>>(
        xn, D_, 0,0,  wk, D_, 0,0,  k, D_, 0,0,  bk, nullptr, D_, 1.f);
    gemm2<128,256,2,4,true,false,false><<<gp,256,SMEM_BIG>>>(
        xn, D_, 0,0,  wv, D_, 0,0,  v, D_, 0,0,  bv, nullptr, D_, 1.f);

    // 3) transpose V -> [B,H,DK,S]
    vtrans_kernel<<<dim3(S_/32, DK_/32, B_*H_), dim3(32,8)>>>();

    // 4) scores = Q K^T / sqrt(64), per (b,h)
    dim3 gs(S_/256, S_/128, B_*H_);
    gemm2<128,256,2,4,false,false,false><<<gs,256,SMEM_BIG>>>(
        q,  D_, (long)S_*D_, DK_,
        k,  D_, (long)S_*D_, DK_,
        sc, S_, (long)H_*S_*S_, (long)S_*S_,
        nullptr, nullptr, DK_, 0.125f);

    // 5) masked softmax (in place)
    softmax_kernel<<<dim3(S_, B_*H_), 256>>>(sc, mask);

    // 6) attention out = P @ V, per (b,h): [2048,2048] @ [2048,64]^T(vt)
    dim3 gpv(1, S_/128, B_*H_);
    gemm2<128,64,2,4,false,false,false><<<gpv,256,SMEM_PV>>>(
        sc, S_, (long)H_*S_*S_, (long)S_*S_,
        vt, S_, (long)H_*DK_*S_, (long)DK_*S_,
        ao, D_, (long)S_*D_, DK_,
        nullptr, nullptr, S_, 1.f);

    // 7) O projection + residual x
    gemm2<128,256,2,4,true,false,true><<<gp,256,SMEM_BIG>>>(
        ao, D_, 0,0,  wo, D_, 0,0,  h, D_, 0,0,  bo, x, D_, 1.f);

    // 8) LN2
    ln_kernel<<<M_, 256>>>(h, a2, c2, hn);

    // 9) FFN1 + ReLU: [8192,1024] @ [4096,1024]^T
    dim3 gf1(DFF_/256, M_/128, 1);
    gemm2<128,256,2,4,true,true,false><<<gf1,256,SMEM_BIG>>>(
        hn, D_, 0,0,  w1, D_, 0,0,  f1, DFF_, 0,0,  b1, nullptr, D_, 1.f);

    // 10) FFN2 + residual h -> out
    gemm2<128,256,2,4,true,false,true><<<gp,256,SMEM_BIG>>>(
        f1, DFF_, 0,0,  w2, DFF_, 0,0,  out, D_, 0,0,  b2, h, DFF_, 1.f);
}

// round 3
// speedup vs baseline: 1.3751x; 1.1022x over previous
#include <cuda_runtime.h>
#include <cstdint>

// Problem constants
#define B_    4
#define S_    2048
#define D_    1024
#define H_    16
#define DK_   64
#define DFF_  4096
#define M_    (B_*S_)   // 8192 rows

// ---------------------------------------------------------------------------
// Static device scratch (allocation-free rule)
// ---------------------------------------------------------------------------
__device__ float g_xn[M_*D_];               // LN1 output
__device__ float g_q [M_*D_];
__device__ float g_k [M_*D_];
__device__ float g_v [M_*D_];
__device__ float g_ao[M_*D_];               // attention output [B,S,D]
__device__ float g_h [M_*D_];               // residual 1
__device__ float g_hn[M_*D_];               // LN2 output
__device__ float g_f1[M_*DFF_];             // FFN hidden

// ---------------------------------------------------------------------------
// Helpers
// ---------------------------------------------------------------------------
__device__ __forceinline__ float warpRedSum(float v){
    #pragma unroll
    for (int o=16;o;o>>=1) v += __shfl_xor_sync(0xffffffffu, v, o);
    return v;
}

__device__ __forceinline__ void mma8(float c[4], const uint32_t a[4], const uint32_t b[2]){
    asm volatile(
        "mma.sync.aligned.m16n8k8.row.col.f32.tf32.tf32.f32 "
        "{%0,%1,%2,%3}, {%4,%5,%6,%7}, {%8,%9}, {%0,%1,%2,%3};\n"
        : "+f"(c[0]), "+f"(c[1]), "+f"(c[2]), "+f"(c[3])
        : "r"(a[0]), "r"(a[1]), "r"(a[2]), "r"(a[3]),
          "r"(b[0]), "r"(b[1]));
}

__device__ __forceinline__ void cpa16(uint32_t dst, const void* src){
    asm volatile("cp.async.cg.shared.global [%0], [%1], 16;\n" :: "r"(dst), "l"(src));
}
__device__ __forceinline__ void cpcommit(){ asm volatile("cp.async.commit_group;\n"); }
__device__ __forceinline__ void cpwait1(){ asm volatile("cp.async.wait_group 1;\n"); }
__device__ __forceinline__ void cpwait0(){ asm volatile("cp.async.wait_group 0;\n"); }

// ---------------------------------------------------------------------------
// LayerNorm (torch-style: a*(x-mean)/(std+eps)+c, std unbiased, eps on std)
// ---------------------------------------------------------------------------
__global__ void ln_kernel(const float* __restrict__ x,
                          const float* __restrict__ alpha,
                          const float* __restrict__ beta,
                          float* __restrict__ y)
{
    __shared__ float s1[8], s2[8];
    long row = blockIdx.x;
    const float4* xr = (const float4*)(x + row*(long)D_);
    float4 v = xr[threadIdx.x];
    float sum = v.x+v.y+v.z+v.w;
    float sq  = v.x*v.x+v.y*v.y+v.z*v.z+v.w*v.w;
    int lane = threadIdx.x & 31, w = threadIdx.x >> 5;
    sum = warpRedSum(sum); sq = warpRedSum(sq);
    if (lane==0){ s1[w]=sum; s2[w]=sq; }
    __syncthreads();
    if (w==0){
        float a = (lane<8)? s1[lane] : 0.f;
        float b = (lane<8)? s2[lane] : 0.f;
        a = warpRedSum(a); b = warpRedSum(b);
        if (lane==0){ s1[0]=a; s2[0]=b; }
    }
    __syncthreads();
    float mean = s1[0] * (1.f/D_);
    float var  = (s2[0] - (float)D_*mean*mean) * (1.f/(D_-1));
    var = fmaxf(var, 0.f);
    float inv = alpha[0] / (sqrtf(var) + 1e-6f);
    float c   = beta[0];
    float4 o;
    o.x=(v.x-mean)*inv+c; o.y=(v.y-mean)*inv+c;
    o.z=(v.z-mean)*inv+c; o.w=(v.w-mean)*inv+c;
    ((float4*)(y + row*(long)D_))[threadIdx.x] = o;
}

// ---------------------------------------------------------------------------
// Fused flash attention: per CTA, 128 Q rows of one (b,h).
// Q in registers (pre-scaled by 1/8), K cp.async double-buffered,
// V cp.async + smem transpose, tf32 mma for QK^T and P@V, online softmax.
// mask[b,k]==0 -> score := -1e9 (exactly matches the reference).
// ---------------------------------------------------------------------------
#define KSTR  68      // K tile / Vraw row stride (floats)
#define VTSTR 133     // V^T row stride
#define PSTR  132     // P row stride

// smem float offsets
#define OFF_K    0                    // 2 * 128*68 = 17408
#define OFF_VR   17408                // 128*68 = 8704
#define OFF_VT   (OFF_VR + 8704)     // 64*133 = 8512
#define OFF_P    (OFF_VT + 8512)     // 128*132 = 16896
#define OFF_MUL  (OFF_P + 16896)     // 128
#define OFF_ADD  (OFF_MUL + 128)     // 128
#define FA_SMEMF (OFF_ADD + 128)     // 51776 floats = 207104 B

__global__ __launch_bounds__(256, 1) void flash_kernel(
    const float* __restrict__ Q, const float* __restrict__ K,
    const float* __restrict__ V, const int* __restrict__ mask,
    float* __restrict__ O)
{
    extern __shared__ float sm[];
    const int tid = threadIdx.x, lane = tid & 31, w = tid >> 5;
    const int g = lane >> 2, tg = lane & 3;
    const int bh = blockIdx.y, b = bh >> 4, h = bh & 15;
    const int hcol = h * DK_;
    const int qbase = blockIdx.x * 128;
    const long rowB = (long)b * S_;

    uint32_t sbase = (uint32_t)__cvta_generic_to_shared(sm);

    // ---- load Q fragments (row-major A), pre-scaled by 1/sqrt(64) ----
    uint32_t qa[8][4];
    {
        const float* q0 = Q + (rowB + qbase + w*16 + g)*(long)D_ + hcol;
        const float* q8 = q0 + 8*(long)D_;
        #pragma unroll
        for (int ks=0; ks<8; ks++){
            qa[ks][0] = __float_as_uint(q0[ks*8+tg  ]*0.125f);
            qa[ks][1] = __float_as_uint(q8[ks*8+tg  ]*0.125f);
            qa[ks][2] = __float_as_uint(q0[ks*8+tg+4]*0.125f);
            qa[ks][3] = __float_as_uint(q8[ks*8+tg+4]*0.125f);
        }
    }

    // ---- issue K0 + V0 (group 0) ----
    {
        const float* Kg = K + rowB*D_ + hcol;
        const float* Vg = V + rowB*D_ + hcol;
        #pragma unroll
        for (int i=0;i<8;i++){
            int idx = i*256 + tid, r = idx >> 4, c4 = idx & 15;
            cpa16(sbase + (uint32_t)((OFF_K + r*KSTR + c4*4)*4),
                  Kg + (long)r*D_ + c4*4);
        }
        #pragma unroll
        for (int i=0;i<8;i++){
            int idx = i*256 + tid, r = idx >> 4, c4 = idx & 15;
            cpa16(sbase + (uint32_t)((OFF_VR + r*KSTR + c4*4)*4),
                  Vg + (long)r*D_ + c4*4);
        }
        cpcommit();
    }

    float o_acc[8][4];
    #pragma unroll
    for (int j=0;j<8;j++){ o_acc[j][0]=0.f;o_acc[j][1]=0.f;o_acc[j][2]=0.f;o_acc[j][3]=0.f; }
    float m0 = -__int_as_float(0x7f800000), m1 = m0;   // -inf
    float l0 = 0.f, l1 = 0.f;

    const int NT = S_ / 128;   // 16
    for (int it = 0; it < NT; it++){
        const int buf = it & 1;
        __syncthreads();                              // prev iter: vt/P/mask done

        // issue next K tile
        if (it+1 < NT){
            const float* Kg = K + (rowB + (it+1)*128)*(long)D_ + hcol;
            #pragma unroll
            for (int i=0;i<8;i++){
                int idx = i*256 + tid, r = idx >> 4, c4 = idx & 15;
                cpa16(sbase + (uint32_t)((OFF_K + (buf^1)*8704 + r*KSTR + c4*4)*4),
                      Kg + (long)r*D_ + c4*4);
            }
        }
        cpcommit();
        cpwait1();                                    // K_it + V_it arrived

        // mask tile -> mult01/add
        if (tid < 128){
            int mv = mask[rowB + it*128 + tid];
            sm[OFF_MUL + tid] = mv ? 1.f : 0.f;
            sm[OFF_ADD + tid] = mv ? 0.f : -1e9f;
        }
        // transpose Vraw[kv][dk] -> vt[dk][kv]
        #pragma unroll
        for (int i=0;i<8;i++){
            int f4 = i*256 + tid, kv = f4 >> 4, d4 = f4 & 15;
            float4 vv = *(const float4*)(sm + OFF_VR + kv*KSTR + d4*4);
            float* col = sm + OFF_VT + kv;
            col[(d4*4+0)*VTSTR] = vv.x;
            col[(d4*4+1)*VTSTR] = vv.y;
            col[(d4*4+2)*VTSTR] = vv.z;
            col[(d4*4+3)*VTSTR] = vv.w;
        }
        __syncthreads();                              // vt+mask ready, vraw free

        // issue next V tile into vraw
        if (it+1 < NT){
            const float* Vg = V + (rowB + (it+1)*128)*(long)D_ + hcol;
            #pragma unroll
            for (int i=0;i<8;i++){
                int idx = i*256 + tid, r = idx >> 4, c4 = idx & 15;
                cpa16(sbase + (uint32_t)((OFF_VR + r*KSTR + c4*4)*4),
                      Vg + (long)r*D_ + c4*4);
            }
        }
        cpcommit();

        // ---- scores: S = Q K^T (16 q rows per warp x 128 kv) ----
        float c[16][4];
        #pragma unroll
        for (int j=0;j<16;j++){ c[j][0]=0.f;c[j][1]=0.f;c[j][2]=0.f;c[j][3]=0.f; }
        const float* Ksb = sm + OFF_K + buf*8704;
        #pragma unroll
        for (int ks=0; ks<8; ks++){
            #pragma unroll
            for (int j=0;j<16;j++){
                uint32_t bb[2];
                bb[0] = __float_as_uint(Ksb[(j*8+g)*KSTR + ks*8+tg  ]);
                bb[1] = __float_as_uint(Ksb[(j*8+g)*KSTR + ks*8+tg+4]);
                mma8(c[j], qa[ks], bb);
            }
        }

        // ---- mask + online softmax ----
        float mx0 = -3.0e38f, mx1 = -3.0e38f;
        #pragma unroll
        for (int j=0;j<16;j++){
            int c0 = j*8 + 2*tg;
            float mu0 = sm[OFF_MUL+c0], mu1 = sm[OFF_MUL+c0+1];
            float ad0 = sm[OFF_ADD+c0], ad1 = sm[OFF_ADD+c0+1];
            c[j][0] = fmaf(c[j][0], mu0, ad0);
            c[j][1] = fmaf(c[j][1], mu1, ad1);
            c[j][2] = fmaf(c[j][2], mu0, ad0);
            c[j][3] = fmaf(c[j][3], mu1, ad1);
            mx0 = fmaxf(mx0, fmaxf(c[j][0], c[j][1]));
            mx1 = fmaxf(mx1, fmaxf(c[j][2], c[j][3]));
        }
        mx0 = fmaxf(mx0, __shfl_xor_sync(0xffffffffu, mx0, 1));
        mx0 = fmaxf(mx0, __shfl_xor_sync(0xffffffffu, mx0, 2));
        mx1 = fmaxf(mx1, __shfl_xor_sync(0xffffffffu, mx1, 1));
        mx1 = fmaxf(mx1, __shfl_xor_sync(0xffffffffu, mx1, 2));

        float nm0 = fmaxf(m0, mx0), nm1 = fmaxf(m1, mx1);
        float cr0 = __expf(m0 - nm0), cr1 = __expf(m1 - nm1);
        float s0 = 0.f, s1 = 0.f;
        #pragma unroll
        for (int j=0;j<16;j++){
            c[j][0] = __expf(c[j][0] - nm0);
            c[j][1] = __expf(c[j][1] - nm0);
            c[j][2] = __expf(c[j][2] - nm1);
            c[j][3] = __expf(c[j][3] - nm1);
            s0 += c[j][0] + c[j][1];
            s1 += c[j][2] + c[j][3];
        }
        s0 += __shfl_xor_sync(0xffffffffu, s0, 1);
        s0 += __shfl_xor_sync(0xffffffffu, s0, 2);
        s1 += __shfl_xor_sync(0xffffffffu, s1, 1);
        s1 += __shfl_xor_sync(0xffffffffu, s1, 2);
        l0 = l0*cr0 + s0;  l1 = l1*cr1 + s1;
        m0 = nm0;          m1 = nm1;
        #pragma unroll
        for (int j=0;j<8;j++){
            o_acc[j][0]*=cr0; o_acc[j][1]*=cr0; o_acc[j][2]*=cr1; o_acc[j][3]*=cr1;
        }

        // ---- write P to smem (per-warp rows, warp-private) ----
        {
            float* Pr0 = sm + OFF_P + (w*16+g)*PSTR + 2*tg;
            float* Pr8 = Pr0 + 8*PSTR;
            #pragma unroll
            for (int j=0;j<16;j++){
                *(float2*)(Pr0 + j*8) = make_float2(c[j][0], c[j][1]);
                *(float2*)(Pr8 + j*8) = make_float2(c[j][2], c[j][3]);
            }
        }
        __syncwarp();

        // ---- O += P @ V  (contraction over 128 kv) ----
        {
            const float* Pw = sm + OFF_P + (w*16)*PSTR;
            #pragma unroll
            for (int kk=0; kk<16; kk++){
                uint32_t a[4];
                a[0] = __float_as_uint(Pw[ g    *PSTR + kk*8+tg  ]);
                a[1] = __float_as_uint(Pw[(g+8)*PSTR + kk*8+tg  ]);
                a[2] = __float_as_uint(Pw[ g    *PSTR + kk*8+tg+4]);
                a[3] = __float_as_uint(Pw[(g+8)*PSTR + kk*8+tg+4]);
                #pragma unroll
                for (int jo=0; jo<8; jo++){
                    uint32_t bb[2];
                    bb[0] = __float_as_uint(sm[OFF_VT + (jo*8+g)*VTSTR + kk*8+tg  ]);
                    bb[1] = __float_as_uint(sm[OFF_VT + (jo*8+g)*VTSTR + kk*8+tg+4]);
                    mma8(o_acc[jo], a, bb);
                }
            }
        }
    }

    // ---- epilogue: O / l ----
    float inv0 = 1.f / l0, inv1 = 1.f / l1;
    float* o0 = O + (rowB + qbase + w*16 + g)*(long)D_ + hcol + 2*tg;
    float* o8 = o0 + 8*(long)D_;
    #pragma unroll
    for (int jo=0; jo<8; jo++){
        *(float2*)(o0 + jo*8) = make_float2(o_acc[jo][0]*inv0, o_acc[jo][1]*inv0);
        *(float2*)(o8 + jo*8) = make_float2(o_acc[jo][2]*inv1, o_acc[jo][3]*inv1);
    }
}

// ---------------------------------------------------------------------------
// NT GEMM, tf32 tensor cores, cp.async double-buffered (unchanged from R2)
// ---------------------------------------------------------------------------
template<int BM,int BN,int WR,int WC,bool HAS_BIAS,bool RELU,bool HAS_RESID>
__global__ __launch_bounds__(WR*WC*32, 1) void gemm2(
    const float* __restrict__ A, int lda,
    const float* __restrict__ Bm, int ldb,
    float* __restrict__ C, int ldc,
    const float* __restrict__ bias, const float* __restrict__ resid,
    int K, float scale)
{
    constexpr int BK = 32, LDSW = 36;
    constexpr int NT = WR*WC*32;
    constexpr int WM = BM/WR, WN = BN/WC;
    constexpr int MF = WM/16, NF = WN/8;
    constexpr int ASZ = BM*LDSW, BSZ = BN*LDSW;

    extern __shared__ float smemf[];
    float* As = smemf;
    float* Bs = smemf + 2*ASZ;

    const float* Ab = A;
    const float* Bb = Bm;

    int tid = threadIdx.x, lane = tid & 31, warp = tid >> 5;
    int g = lane >> 2, tg = lane & 3;
    int wm = warp / WC, wn = warp % WC;
    int m0 = blockIdx.y * BM, n0 = blockIdx.x * BN;

    uint32_t sbase = (uint32_t)__cvta_generic_to_shared(smemf);

    float acc[MF][NF][4];
    #pragma unroll
    for (int i=0;i<MF;i++)
        #pragma unroll
        for (int j=0;j<NF;j++)
            #pragma unroll
            for (int r=0;r<4;r++) acc[i][j][r] = 0.f;

    auto loadt = [&](int k0, int buf){
        #pragma unroll
        for (int i = 0; i < BM*8; i += NT){
            int idx = i + tid; int r = idx >> 3, c = idx & 7;
            cpa16(sbase + (uint32_t)((buf*ASZ + r*LDSW + c*4)*4),
                  Ab + (long)(m0+r)*lda + k0 + c*4);
        }
        #pragma unroll
        for (int i = 0; i < BN*8; i += NT){
            int idx = i + tid; int r = idx >> 3, c = idx & 7;
            cpa16(sbase + (uint32_t)((2*ASZ + buf*BSZ + r*LDSW + c*4)*4),
                  Bb + (long)(n0+r)*ldb + k0 + c*4);
        }
        cpcommit();
    };

    int nt = K / BK;
    loadt(0, 0);

    for (int k0 = 0; k0 < nt; k0++){
        int cur = k0 & 1;
        if (k0+1 < nt){
            loadt((k0+1)*BK, cur^1);
            cpwait1();
        } else {
            cpwait0();
        }
        __syncthreads();

        const float* Asb = As + cur*ASZ;
        const float* Bsb = Bs + cur*BSZ;

        #pragma unroll
        for (int ks = 0; ks < BK; ks += 8){
            uint32_t af[MF][4], bf[NF][2];
            #pragma unroll
            for (int im=0; im<MF; im++){
                int r = wm*WM + im*16 + g;
                af[im][0] = __float_as_uint(Asb[r*LDSW + ks+tg  ]);
                af[im][1] = __float_as_uint(Asb[(r+8)*LDSW + ks+tg  ]);
                af[im][2] = __float_as_uint(Asb[r*LDSW + ks+tg+4]);
                af[im][3] = __float_as_uint(Asb[(r+8)*LDSW + ks+tg+4]);
            }
            #pragma unroll
            for (int jn=0; jn<NF; jn++){
                int r = wn*WN + jn*8 + g;
                bf[jn][0] = __float_as_uint(Bsb[r*LDSW + ks+tg  ]);
                bf[jn][1] = __float_as_uint(Bsb[r*LDSW + ks+tg+4]);
            }
            #pragma unroll
            for (int im=0; im<MF; im++)
                #pragma unroll
                for (int jn=0; jn<NF; jn++)
                    mma8(acc[im][jn], af[im], bf[jn]);
        }
        __syncthreads();
    }

    #pragma unroll
    for (int im=0; im<MF; im++){
        int r0 = m0 + wm*WM + im*16 + g;
        #pragma unroll
        for (int jn=0; jn<NF; jn++){
            int c0 = n0 + wn*WN + jn*8 + tg*2;
            float2 bv = HAS_BIAS ? *(const float2*)(bias + c0) : make_float2(0.f,0.f);
            float2 v0, v1;
            v0.x = acc[im][jn][0]*scale + bv.x;
            v0.y = acc[im][jn][1]*scale + bv.y;
            v1.x = acc[im][jn][2]*scale + bv.x;
            v1.y = acc[im][jn][3]*scale + bv.y;
            if (RELU){
                v0.x = fmaxf(v0.x,0.f); v0.y = fmaxf(v0.y,0.f);
                v1.x = fmaxf(v1.x,0.f); v1.y = fmaxf(v1.y,0.f);
            }
            if (HAS_RESID){
                float2 ra = *(const float2*)(resid + (long)r0*ldc + c0);
                float2 rb = *(const float2*)(resid + (long)(r0+8)*ldc + c0);
                v0.x += ra.x; v0.y += ra.y; v1.x += rb.x; v1.y += rb.y;
            }
            *(float2*)(C + (long)r0*ldc + c0)     = v0;
            *(float2*)(C + (long)(r0+8)*ldc + c0) = v1;
        }
    }
}

// ---------------------------------------------------------------------------
// Launch
// ---------------------------------------------------------------------------
extern "C" void kernel_launch(void* const* d_in, const int* in_sizes, int n_in,
                              void* d_out, int out_size)
{
    const float* x    = (const float*)d_in[0];
    const int*   mask = (const int*)  d_in[1];
    const float* wq = (const float*)d_in[2];  const float* bq = (const float*)d_in[3];
    const float* wk = (const float*)d_in[4];  const float* bk = (const float*)d_in[5];
    const float* wv = (const float*)d_in[6];  const float* bv = (const float*)d_in[7];
    const float* wo = (const float*)d_in[8];  const float* bo = (const float*)d_in[9];
    const float* w1 = (const float*)d_in[10]; const float* b1 = (const float*)d_in[11];
    const float* w2 = (const float*)d_in[12]; const float* b2 = (const float*)d_in[13];
    const float* a1 = (const float*)d_in[14]; const float* c1 = (const float*)d_in[15];
    const float* a2 = (const float*)d_in[16]; const float* c2 = (const float*)d_in[17];
    float* out = (float*)d_out;

    void* p;
    float *xn,*q,*k,*v,*ao,*h,*hn,*f1;
    cudaGetSymbolAddress(&p, g_xn); xn = (float*)p;
    cudaGetSymbolAddress(&p, g_q ); q  = (float*)p;
    cudaGetSymbolAddress(&p, g_k ); k  = (float*)p;
    cudaGetSymbolAddress(&p, g_v ); v  = (float*)p;
    cudaGetSymbolAddress(&p, g_ao); ao = (float*)p;
    cudaGetSymbolAddress(&p, g_h ); h  = (float*)p;
    cudaGetSymbolAddress(&p, g_hn); hn = (float*)p;
    cudaGetSymbolAddress(&p, g_f1); f1 = (float*)p;

    constexpr int SMEM_BIG = (2*128 + 2*256)*36*4;   // 110592 B
    constexpr int SMEM_FA  = FA_SMEMF*4;             // 207104 B

    cudaFuncSetAttribute((const void*)gemm2<128,256,2,4,true ,false,false>,
                         cudaFuncAttributeMaxDynamicSharedMemorySize, SMEM_BIG);
    cudaFuncSetAttribute((const void*)gemm2<128,256,2,4,true ,false,true >,
                         cudaFuncAttributeMaxDynamicSharedMemorySize, SMEM_BIG);
    cudaFuncSetAttribute((const void*)gemm2<128,256,2,4,true ,true ,false>,
                         cudaFuncAttributeMaxDynamicSharedMemorySize, SMEM_BIG);
    cudaFuncSetAttribute((const void*)flash_kernel,
                         cudaFuncAttributeMaxDynamicSharedMemorySize, SMEM_FA);

    // 1) LN1
    ln_kernel<<<M_, 256>>>(x, a1, c1, xn);

    // 2) Q, K, V projections: [8192,1024] @ [1024,1024]^T
    dim3 gp(D_/256, M_/128, 1);
    gemm2<128,256,2,4,true,false,false><<<gp,256,SMEM_BIG>>>(
        xn, D_, wq, D_, q, D_, bq, nullptr, D_, 1.f);
    gemm2<128,256,2,4,true,false,false><<<gp,256,SMEM_BIG>>>(
        xn, D_, wk, D_, k, D_, bk, nullptr, D_, 1.f);
    gemm2<128,256,2,4,true,false,false><<<gp,256,SMEM_BIG>>>(
        xn, D_, wv, D_, v, D_, bv, nullptr, D_, 1.f);

    // 3) fused flash attention -> g_ao
    flash_kernel<<<dim3(S_/128, B_*H_), 256, SMEM_FA>>>(q, k, v, mask, ao);

    // 4) O projection + residual x
    gemm2<128,256,2,4,true,false,true><<<gp,256,SMEM_BIG>>>(
        ao, D_, wo, D_, h, D_, bo, x, D_, 1.f);

    // 5) LN2
    ln_kernel<<<M_, 256>>>(h, a2, c2, hn);

    // 6) FFN1 + ReLU: [8192,1024] @ [4096,1024]^T
    dim3 gf1(DFF_/256, M_/128, 1);
    gemm2<128,256,2,4,true,true,false><<<gf1,256,SMEM_BIG>>>(
        hn, D_, w1, D_, f1, DFF_, b1, nullptr, D_, 1.f);

    // 7) FFN2 + residual h -> out
    gemm2<128,256,2,4,true,false,true><<<gp,256,SMEM_BIG>>>(
        f1, DFF_, w2, DFF_, out, D_, b2, h, DFF_, 1.f);
}